// round 5
// baseline (speedup 1.0000x reference)
#include <cuda_runtime.h>
#include <math.h>

// Problem dims
#define Bn 512
#define Tn 256
#define Vn 128
#define Hn 512
#define TB (Tn*Bn)      // 131072 rows
#define NOUT 1536       // r(512) | z(512) | h(512) pre-activation columns
#define NBLK 128

// ---------------- device scratch (no allocations allowed) ----------------
__device__ float g_vT[TB*Vn];
__device__ float g_mT[TB*Vn];
__device__ float g_dT[TB*Vn];
__device__ float g_xmean[TB*Vn];
__device__ float g_xp[TB*Vn];
__device__ float g_xt[TB*Vn];
__device__ float g_A[(size_t)TB*NOUT];   // bulk pre-activations (xt,mt,bias parts)
__device__ float g_Dh[(size_t)TB*Hn];    // delta_h for all t
__device__ float g_Wcat[NOUT*256];       // [x|m] columns of Wr,Wz,Wh packed
__device__ float g_bcat[NOUT];
__device__ float g_Wrz[1024*512];        // h-columns of Wr(0..511), Wz(512..1023)
__device__ float g_Whh[512*512];         // h-columns of Wh
__device__ float g_hbuf[Bn*Hn];          // decayed hidden state Dh[t]*h
__device__ float g_rh[Bn*Hn];            // r * h_decayed
__device__ float g_z[Bn*Hn];             // z gate

// grid barrier state (monotonic generation -> replay safe)
__device__ unsigned g_barc;
__device__ volatile unsigned g_barg;

// ---------------- tf32 helpers ----------------
__device__ __forceinline__ void tf32_split(float x, float& hi, float& lo)
{
    unsigned hu; asm("cvt.rna.tf32.f32 %0, %1;" : "=r"(hu) : "f"(x));
    hi = __uint_as_float(hu);
    float r = x - hi;
    unsigned lu; asm("cvt.rna.tf32.f32 %0, %1;" : "=r"(lu) : "f"(r));
    lo = __uint_as_float(lu);
}

__device__ __forceinline__ void mma_f4(float c[4], float4 a, float bx, float by)
{
    asm volatile("mma.sync.aligned.m16n8k8.row.col.f32.tf32.tf32.f32 "
        "{%0,%1,%2,%3},{%4,%5,%6,%7},{%8,%9},{%0,%1,%2,%3};"
        : "+f"(c[0]), "+f"(c[1]), "+f"(c[2]), "+f"(c[3])
        : "r"(__float_as_uint(a.x)), "r"(__float_as_uint(a.y)),
          "r"(__float_as_uint(a.z)), "r"(__float_as_uint(a.w)),
          "r"(__float_as_uint(bx)),  "r"(__float_as_uint(by)));
}

// Stage ROWS x 32 A-chunk into fragment-packed smem (hi/lo split).
// Fragment layout (m16k8 tile): lane = ((m&7)<<2)|(k&3), slot = ((m>>3)&1)|(((k>>2)&1)<<1)
template<int ROWS>
__device__ __forceinline__ void stageA32(const float* __restrict__ src, int lda,
                                         float* as_hi, float* as_lo, int tid)
{
#pragma unroll
    for (int l = 0; l < ROWS/32; l++) {
        int i = tid + l*256;
        int row = i >> 3, c4 = (i & 7) << 2;
        float4 v = *(const float4*)(src + (size_t)row*lda + c4);
        float xs[4] = {v.x, v.y, v.z, v.w};
#pragma unroll
        for (int j = 0; j < 4; j++) {
            int kk = c4 + j;
            float hi, lo; tf32_split(xs[j], hi, lo);
            int fr = row >> 4, fk = kk >> 3;
            int ln = ((row & 7) << 2) | (kk & 3);
            int sl = ((row >> 3) & 1) | (((kk >> 2) & 1) << 1);
            int base = ((fr*4 + fk)*32 + ln)*4 + sl;
            as_hi[base] = hi;
            as_lo[base] = lo;
        }
    }
}

// Stage ROWS x 32 B-chunk (B = W[n][k] row-major == k8n8 col-major fragments).
// lane = ((n&7)<<2)|(k&3), slot = (k>>2)&1;  [lane][hi0,hi1,lo0,lo1]
template<int ROWS>
__device__ __forceinline__ void stageB32(const float* __restrict__ src, int ldb,
                                         float* bs, int tid)
{
#pragma unroll
    for (int l = 0; l < ROWS/32; l++) {
        int i = tid + l*256;
        int row = i >> 3, c4 = (i & 7) << 2;
        float4 v = *(const float4*)(src + (size_t)row*ldb + c4);
        float xs[4] = {v.x, v.y, v.z, v.w};
#pragma unroll
        for (int j = 0; j < 4; j++) {
            int kk = c4 + j;
            float hi, lo; tf32_split(xs[j], hi, lo);
            int fn = row >> 3, fk = kk >> 3;
            int ln = ((row & 7) << 2) | (kk & 3);
            int sl = (kk >> 2) & 1;
            int base = ((fn*4 + fk)*32 + ln)*4;
            bs[base + sl]     = hi;
            bs[base + 2 + sl] = lo;
        }
    }
}

// Compute one 32-wide K chunk. Warp tile = 32m x (NF*8)n. TF32x3.
template<int NF>
__device__ __forceinline__ void compute32(const float* as_hi, const float* as_lo,
                                          const float* bs, int wy, int wx, int lane,
                                          float c[][NF][4])
{
#pragma unroll
    for (int fk = 0; fk < 4; fk++) {
        float4 ah[2], al[2];
#pragma unroll
        for (int mf = 0; mf < 2; mf++) {
            int base = (((wy*2 + mf)*4 + fk)*32 + lane)*4;
            ah[mf] = *(const float4*)(as_hi + base);
            al[mf] = *(const float4*)(as_lo + base);
        }
#pragma unroll
        for (int nf = 0; nf < NF; nf++) {
            int bbase = (((wx*NF + nf)*4 + fk)*32 + lane)*4;
            float4 bb = *(const float4*)(bs + bbase);
#pragma unroll
            for (int mf = 0; mf < 2; mf++) {
                mma_f4(c[mf][nf], ah[mf], bb.x, bb.y);  // hi*hi
                mma_f4(c[mf][nf], ah[mf], bb.z, bb.w);  // hi*lo
                mma_f4(c[mf][nf], al[mf], bb.x, bb.y);  // lo*hi
            }
        }
    }
}

// ---------------- weight packing ----------------
__global__ void pack_weights(const float* __restrict__ Wz, const float* __restrict__ bz,
                             const float* __restrict__ Wr, const float* __restrict__ br,
                             const float* __restrict__ Wh, const float* __restrict__ bh)
{
    int i = blockIdx.x * blockDim.x + threadIdx.x;
    if (i < NOUT*256) {
        int n = i >> 8, k = i & 255;
        const float* W = (n < 512) ? Wr : ((n < 1024) ? Wz : Wh);
        int row = (n < 512) ? n : ((n < 1024) ? n - 512 : n - 1024);
        int col = (k < 128) ? k : (k + 512);
        g_Wcat[i] = W[row*768 + col];
        return;
    }
    int j = i - NOUT*256;
    if (j >= 0 && j < 1024*512) {
        int n = j >> 9, k = j & 511;
        g_Wrz[j] = (n < 512) ? Wr[n*768 + 128 + k] : Wz[(n-512)*768 + 128 + k];
        return;
    }
    int l = j - 1024*512;
    if (l >= 0 && l < 512*512) {
        int n = l >> 9, k = l & 511;
        g_Whh[l] = Wh[n*768 + 128 + k];
        return;
    }
    int m = l - 512*512;
    if (m >= 0 && m < NOUT) {
        g_bcat[m] = (m < 512) ? br[m] : ((m < 1024) ? bz[m-512] : bh[m-1024]);
    }
}

// ---------------- P0: transpose + cumulative mean + x_prime recurrence ----------------
__global__ void p0_kernel(const float* __restrict__ vals,
                          const float* __restrict__ masks,
                          const float* __restrict__ past)
{
    int idx = blockIdx.x * blockDim.x + threadIdx.x;
    if (idx >= Bn*Vn) return;
    int b = idx / Vn, v = idx % Vn;
    const float* vp = vals  + (size_t)b*Tn*Vn + v;
    const float* mp = masks + (size_t)b*Tn*Vn + v;
    const float* dp = past  + (size_t)b*Tn*Vn + v;
    float cmv = 0.f, cm = 0.f, xp = 0.f;
    for (int t = 0; t < Tn; t++) {
        float x = vp[t*Vn], m = mp[t*Vn], d = dp[t*Vn];
        cmv += m * x;
        cm  += m;
        float xmean = (cm > 0.f) ? (cmv / cm) : 0.f;
        xp = m * x + (1.f - m) * xp;
        int o = (t*Bn + b)*Vn + v;
        g_vT[o] = x; g_mT[o] = m; g_dT[o] = d;
        g_xmean[o] = xmean; g_xp[o] = xp;
    }
}

// ---------------- bulk tensor GEMMs (block 128m x 64n, warps 4x2, warp 32x32) --------
// MODE 0: A=[xt|mT] K=256, B=g_Wcat -> g_A = . + bias
// MODE 1: A=g_dT   K=128, B=Wgh    -> g_Dh = exp(-relu(.+bgh))
// MODE 2: A=g_dT   K=128, B=Wgx    -> g_xt composite epilogue
template<int MODE>
__global__ void __launch_bounds__(256) gemm_tc(const float* __restrict__ Wsrc,
                                               const float* __restrict__ bias)
{
    constexpr int KDIM = (MODE == 0) ? 256 : 128;
    __shared__ float as_hi[8*4*32*4];
    __shared__ float as_lo[8*4*32*4];
    __shared__ float bs[8*4*32*4];
    const int tid = threadIdx.x, lane = tid & 31, wid = tid >> 5;
    const int wy = wid >> 1, wx = wid & 1;     // 4 m-warps x 2 n-warps
    const int n0 = blockIdx.x * 64;
    const int m0 = blockIdx.y * 128;
    const float* Wp = (MODE == 0) ? g_Wcat : Wsrc;
    const float* bp = (MODE == 0) ? g_bcat : bias;

    float c[2][4][4];
#pragma unroll
    for (int a = 0; a < 2; a++)
#pragma unroll
        for (int b = 0; b < 4; b++)
#pragma unroll
            for (int d = 0; d < 4; d++) c[a][b][d] = 0.f;

    for (int kc = 0; kc < KDIM; kc += 32) {
        const float* Asrc;
        if (MODE == 0)
            Asrc = (kc < 128) ? (g_xt + (size_t)m0*Vn + kc)
                              : (g_mT + (size_t)m0*Vn + (kc - 128));
        else
            Asrc = g_dT + (size_t)m0*Vn + kc;
        stageA32<128>(Asrc, Vn, as_hi, as_lo, tid);
        stageB32<64>(Wp + (size_t)n0*KDIM + kc, KDIM, bs, tid);
        __syncthreads();
        compute32<4>(as_hi, as_lo, bs, wy, wx, lane, c);
        __syncthreads();
    }

    const int r = lane >> 2, cl = lane & 3;
#pragma unroll
    for (int mf = 0; mf < 2; mf++)
#pragma unroll
    for (int nf = 0; nf < 4; nf++)
#pragma unroll
    for (int i = 0; i < 4; i++) {
        int m = m0 + wy*32 + mf*16 + r + ((i >> 1) << 3);
        int n = n0 + wx*32 + nf*8 + cl*2 + (i & 1);
        float vv = c[mf][nf][i] + bp[n];
        if (MODE == 0) {
            g_A[(size_t)m*NOUT + n] = vv;
        } else if (MODE == 1) {
            g_Dh[(size_t)m*Hn + n] = expf(-fmaxf(vv, 0.f));
        } else {
            float dx = expf(-fmaxf(vv, 0.f));
            int o = m*Vn + n;
            float mt = g_mT[o], x = g_vT[o], xp = g_xp[o], xm = g_xmean[o];
            g_xt[o] = mt*x + (1.f - mt)*(dx*xp + (1.f - dx)*xm);
        }
    }
}

// ---------------- persistent sequential kernel (tensor) ----------------
__device__ __forceinline__ void gsync()
{
    __syncthreads();
    if (threadIdx.x == 0) {
        __threadfence();
        unsigned gen = g_barg;
        if (atomicAdd(&g_barc, 1u) == NBLK - 1) {
            g_barc = 0;
            __threadfence();
            g_barg = gen + 1;
        } else {
            while (g_barg == gen) { __nanosleep(64); }
        }
        __threadfence();
    }
    __syncthreads();
}

__global__ void __launch_bounds__(256) seq_tc(float* __restrict__ out)
{
    __shared__ float as_hi[4*4*32*4];
    __shared__ float as_lo[4*4*32*4];
    __shared__ float bs[8*4*32*4];
    const int tid = threadIdx.x, lane = tid & 31, wid = tid >> 5;
    const int bx = blockIdx.x;
    const int wy = wid >> 2, wx = wid & 3;   // 2 m-warps x 4 n-warps
    const int r = lane >> 2, cl = lane & 3;

    for (int i = bx*256 + tid; i < Bn*Hn; i += NBLK*256) g_hbuf[i] = 0.f;
    gsync();

    const int m0 = (bx >> 4) * 64;   // 8 m-tiles of 64
    const int n1 = (bx & 15) * 64;   // phase1: 16 n-tiles of 64 (N=1024)
    const int n2 = (bx & 15) * 32;   // phase2: 16 n-tiles of 32 (N=512)

    for (int t = 0; t < Tn; t++) {
        const size_t abase = (size_t)t * Bn * NOUT;
        // ---- phase 1: [64m x 64n] of (hbuf @ Wrz^T); warp 32x16 (NF=2) ----
        {
            float c[2][2][4];
#pragma unroll
            for (int a = 0; a < 2; a++)
#pragma unroll
                for (int b = 0; b < 2; b++)
#pragma unroll
                    for (int d = 0; d < 4; d++) c[a][b][d] = 0.f;
            for (int kc = 0; kc < Hn; kc += 32) {
                stageA32<64>(g_hbuf + (size_t)m0*Hn + kc, Hn, as_hi, as_lo, tid);
                stageB32<64>(g_Wrz + (size_t)n1*Hn + kc, Hn, bs, tid);
                __syncthreads();
                compute32<2>(as_hi, as_lo, bs, wy, wx, lane, c);
                __syncthreads();
            }
#pragma unroll
            for (int mf = 0; mf < 2; mf++)
#pragma unroll
            for (int nf = 0; nf < 2; nf++)
#pragma unroll
            for (int i = 0; i < 4; i++) {
                int m = m0 + wy*32 + mf*16 + r + ((i >> 1) << 3);
                int n = n1 + wx*16 + nf*8 + cl*2 + (i & 1);
                float pre = c[mf][nf][i] + g_A[abase + (size_t)m*NOUT + n];
                float s = 1.f / (1.f + expf(-pre));
                if (n < Hn) g_rh[m*Hn + n] = s * g_hbuf[m*Hn + n];
                else        g_z[m*Hn + n - Hn] = s;
            }
        }
        gsync();
        // ---- phase 2: [64m x 32n] of (rh @ Whh^T); warp 32x8 (NF=1) ----
        {
            float c[2][1][4];
#pragma unroll
            for (int a = 0; a < 2; a++)
#pragma unroll
                for (int d = 0; d < 4; d++) c[a][0][d] = 0.f;
            for (int kc = 0; kc < Hn; kc += 32) {
                stageA32<64>(g_rh + (size_t)m0*Hn + kc, Hn, as_hi, as_lo, tid);
                stageB32<32>(g_Whh + (size_t)n2*Hn + kc, Hn, bs, tid);
                __syncthreads();
                compute32<1>(as_hi, as_lo, bs, wy, wx, lane, c);
                __syncthreads();
            }
            const size_t obase = (size_t)t * Bn * Hn;
            const size_t dbase = (size_t)(t + 1) * Bn * Hn;
#pragma unroll
            for (int mf = 0; mf < 2; mf++)
#pragma unroll
            for (int i = 0; i < 4; i++) {
                int m = m0 + wy*32 + mf*16 + r + ((i >> 1) << 3);
                int n = n2 + wx*8 + cl*2 + (i & 1);
                float pre = c[mf][0][i] + g_A[abase + (size_t)m*NOUT + 1024 + n];
                float ht = tanhf(pre);
                float hd = g_hbuf[m*Hn + n];
                float z  = g_z[m*Hn + n];
                float hn = (1.f - z)*hd + z*ht;
                out[obase + (size_t)m*Hn + n] = hn;
                float dn = (t + 1 < Tn) ? g_Dh[dbase + (size_t)m*Hn + n] : 0.f;
                g_hbuf[m*Hn + n] = dn * hn;
            }
        }
        gsync();
    }
}

// ---------------- launch ----------------
extern "C" void kernel_launch(void* const* d_in, const int* in_sizes, int n_in,
                              void* d_out, int out_size)
{
    const float* vals  = (const float*)d_in[0];
    const float* masks = (const float*)d_in[1];
    const float* past  = (const float*)d_in[2];
    const float* Wz    = (const float*)d_in[3];
    const float* bz    = (const float*)d_in[4];
    const float* Wr    = (const float*)d_in[5];
    const float* br    = (const float*)d_in[6];
    const float* Wh    = (const float*)d_in[7];
    const float* bh    = (const float*)d_in[8];
    const float* Wgx   = (const float*)d_in[9];
    const float* bgx   = (const float*)d_in[10];
    const float* Wgh   = (const float*)d_in[11];
    const float* bgh   = (const float*)d_in[12];
    float* out = (float*)d_out;

    pack_weights<<<4614, 256>>>(Wz, bz, Wr, br, Wh, bh);
    p0_kernel<<<(Bn*Vn + 255)/256, 256>>>(vals, masks, past);
    gemm_tc<1><<<dim3(Hn/64, TB/128), 256>>>(Wgh, bgh);   // delta_h
    gemm_tc<2><<<dim3(Vn/64, TB/128), 256>>>(Wgx, bgx);   // delta_x -> xt
    gemm_tc<0><<<dim3(NOUT/64, TB/128), 256>>>(nullptr, nullptr); // gate pre-acts
    seq_tc<<<NBLK, 256>>>(out);
}